// round 7
// baseline (speedup 1.0000x reference)
#include <cuda_runtime.h>
#include <math.h>
#include <stdint.h>

#define Bb 32
#define Nn 64
#define Dd 256
#define PEN 10000.0f
#define INV_TEMP 20.0f   // 1/0.05

typedef unsigned long long u64;

// ---------------- device scratch (no allocations allowed) ----------------
__device__ float g_A  [Bb*Nn*Dd];   // s_t  @ W1a                   (2 MB)
__device__ float g_Bm [Bb*Nn*Dd];   // s_t1 @ W1b + b1              (2 MB)
__device__ float g_s1T[Bb*Dd*Nn];   // clipped s_t1 transposed [b][k][j] (2 MB)
__device__ float g_la [Bb*Nn*Nn];   // log_alpha                    (512 KB)

__device__ __forceinline__ float clip50(float x){ return fminf(fmaxf(x, -50.f), 50.f); }

__device__ __forceinline__ u64 pack2(float x, float y){
    u64 r; asm("mov.b64 %0, {%1, %2};" : "=l"(r) : "f"(x), "f"(y)); return r;
}
__device__ __forceinline__ void unpack2(u64 v, float &lo, float &hi){
    asm("mov.b64 {%0, %1}, %2;" : "=f"(lo), "=f"(hi) : "l"(v));
}
__device__ __forceinline__ void fma2(u64 &acc, u64 a, u64 b){
    asm("fma.rn.f32x2 %0, %1, %2, %0;" : "+l"(acc) : "l"(a), "l"(b));
}
__device__ __forceinline__ u64 fma2r(u64 a, u64 b, u64 c){
    u64 d; asm("fma.rn.f32x2 %0, %1, %2, %3;" : "=l"(d) : "l"(a), "l"(b), "l"(c)); return d;
}
__device__ __forceinline__ u64 lds64(const float* p){
    return *reinterpret_cast<const u64*>(p);
}
__device__ __forceinline__ void cp_async16(uint32_t dst, const void* src){
    asm volatile("cp.async.ca.shared.global [%0], [%1], 16;" :: "r"(dst), "l"(src));
}
#define CP_COMMIT() asm volatile("cp.async.commit_group;")
#define CP_WAIT2()  asm volatile("cp.async.wait_group 2;")
#define CP_WAIT1()  asm volatile("cp.async.wait_group 1;")
#define CP_WAIT0()  asm volatile("cp.async.wait_group 0;")

// ================= Kernel 1: A = clip(s_t)@W1a ; Bm = clip(s_t1)@W1b + b1 ============
// De-packed: s-tiles stored as duplicated (s,s) u64; W read as contiguous c-pairs.
// grid (4,B), 512 threads. Thread = (c-pair cp = tid&127, rows rb=(tid>>7)*4 .. +3).
#define P_S0D 0                 // u64 [256][17]  (8704 floats)
#define P_S1D 8704              // u64 [256][17]
#define P_WT  17408             // [2 stages][16384 floats]  (32 k x 256 c x 2 mats)
#define P_SMEM_FLOATS (17408 + 32768)
#define P_SMEM_BYTES  (P_SMEM_FLOATS*4)   // 200704

__global__ void __launch_bounds__(512, 1) precompute_kernel(
    const float* __restrict__ slots_t, const float* __restrict__ slots_t1,
    const float* __restrict__ W1, const float* __restrict__ b1)
{
    extern __shared__ float psm[];
    u64* S0D = reinterpret_cast<u64*>(psm + P_S0D);   // [k][r] stride 17 -> (k*17+r)
    u64* S1D = reinterpret_cast<u64*>(psm + P_S1D);
    float* WT = psm + P_WT;
    const u64* WTu = reinterpret_cast<const u64*>(WT);
    const int ig = blockIdx.x, b = blockIdx.y;
    const int tid = threadIdx.x;
    const int rowbase = b*Nn + ig*16;
    const int gbase = rowbase * Dd;
    const uint32_t wt_smem = (uint32_t)__cvta_generic_to_shared(WT);

    // prefetch W stages 0 and 1 (each: 32 k-rows of W1a + 32 of W1b = 64KB)
    #pragma unroll
    for (int t = 0; t < 2; t++){
        #pragma unroll
        for (int u = 0; u < 4; u++){
            int off = u*8192 + tid*16;
            cp_async16(wt_smem + t*65536 + off,         (const char*)(W1 + t*32*Dd) + off);
            cp_async16(wt_smem + t*65536 + 32768 + off, (const char*)(W1 + (256 + t*32)*Dd) + off);
        }
        CP_COMMIT();
    }

    // fill duplicated s-tiles (coalesced global reads: k fast)
    #pragma unroll
    for (int n = 0; n < 8; n++){
        int idx = tid + n*512;
        int r = idx >> 8, k = idx & 255;
        float v0 = clip50(slots_t [gbase + idx]);
        float v1 = clip50(slots_t1[gbase + idx]);
        S0D[k*17 + r] = pack2(v0, v0);
        S1D[k*17 + r] = pack2(v1, v1);
    }
    __syncthreads();

    // write g_s1T [b][k][j]  (j = ig*16 + r); r fast for semi-coalesced global writes
    #pragma unroll
    for (int n = 0; n < 8; n++){
        int idx = tid + n*512;
        int r = idx & 15, k = idx >> 4;
        float v = *reinterpret_cast<const float*>(&S1D[k*17 + r]);   // low half
        g_s1T[(b*256 + k)*64 + ig*16 + r] = v;
    }

    const int cp = tid & 127;           // c-pair: c = 2cp, 2cp+1
    const int rb = (tid >> 7) * 4;      // 4 local rows
    u64 accA[4], accB[4];
    #pragma unroll
    for (int p=0;p<4;p++){ accA[p]=0ULL; accB[p]=0ULL; }

    for (int t = 0; t < 8; t++){
        if (t < 7) { CP_WAIT1(); } else { CP_WAIT0(); }
        __syncthreads();
        const u64* WS = WTu + (t&1)*8192;          // stage base (u64 units)
        #pragma unroll 8
        for (int kk = 0; kk < 32; kk++){
            const int k = t*32 + kk;
            u64 wA = WS[kk*128 + cp];              // (W1a[k][2cp], W1a[k][2cp+1])
            u64 wB = WS[4096 + kk*128 + cp];       // (W1b[k][2cp], W1b[k][2cp+1])
            #pragma unroll
            for (int p=0;p<4;p++){
                fma2(accA[p], S0D[k*17 + rb + p], wA);
                fma2(accB[p], S1D[k*17 + rb + p], wB);
            }
        }
        __syncthreads();
        if (t + 2 < 8){
            const int tn = t + 2;
            #pragma unroll
            for (int u = 0; u < 4; u++){
                int off = u*8192 + tid*16;
                cp_async16(wt_smem + (tn&1)*65536 + off,         (const char*)(W1 + tn*32*Dd) + off);
                cp_async16(wt_smem + (tn&1)*65536 + 32768 + off, (const char*)(W1 + (256 + tn*32)*Dd) + off);
            }
            CP_COMMIT();
        }
    }

    const float2 b1p = *reinterpret_cast<const float2*>(&b1[2*cp]);
    #pragma unroll
    for (int p=0;p<4;p++){
        float lo, hi;
        unpack2(accA[p], lo, hi);
        *reinterpret_cast<float2*>(&g_A[(rowbase + rb + p)*Dd + 2*cp]) = make_float2(lo, hi);
        unpack2(accB[p], lo, hi);
        *reinterpret_cast<float2*>(&g_Bm[(rowbase + rb + p)*Dd + 2*cp]) = make_float2(lo + b1p.x, hi + b1p.y);
    }
}

// ================= Kernel 2: per (b,i) scores for all j -> log_alpha ===============
// De-packed GEMM1: DD stores duplicated (d,d); weights as contiguous c-pairs.
#define SOFF_ST1T 0        // u64 [256][32] (16384 floats); later W2P u64[128][64]
#define SOFF_H    16384    // [64][256]
#define SOFF_SCR  32768    // 2 x [16][256] W1c ping-pong (8192 floats); later H2 [64][64]
#define SOFF_DD   40960    // u64 [2][16][64] duplicated (4096 floats)
#define SOFF_STIP 45056    // u64 [256] (a,a)
#define SOFF_AB   45568    // [256]
#define SOFF_W3   45824    // [64]
#define SOFF_B2   45888    // [64]
#define S_SMEM_FLOATS 45952
#define S_SMEM_BYTES  (S_SMEM_FLOATS*4)   // 183808

__global__ void __launch_bounds__(512, 1) score_kernel(
    const float* __restrict__ slots_t,
    const float* __restrict__ alive_t, const float* __restrict__ alive_t1,
    const float* __restrict__ W1,
    const float* __restrict__ W2, const float* __restrict__ b2,
    const float* __restrict__ W3, const float* __restrict__ b3)
{
    extern __shared__ float sm[];
    float* H    = sm + SOFF_H;
    float* SCR  = sm + SOFF_SCR;
    float* AB   = sm + SOFF_AB;
    float* W3S  = sm + SOFF_W3;
    float* B2S  = sm + SOFF_B2;
    u64* ST1Tu = reinterpret_cast<u64*>(sm + SOFF_ST1T);
    u64* SCRu  = reinterpret_cast<u64*>(sm + SOFF_SCR);
    u64* DDu   = reinterpret_cast<u64*>(sm + SOFF_DD);
    u64* STIPu = reinterpret_cast<u64*>(sm + SOFF_STIP);

    const int i = blockIdx.x, b = blockIdx.y;
    const int tid = threadIdx.x;
    const int tx = tid & 31, w = tid >> 5;
    const int jb = w * 4;                     // warp owns j = jb..jb+3

    const uint32_t st1t_smem = (uint32_t)__cvta_generic_to_shared(sm + SOFF_ST1T);
    const uint32_t scr_smem  = (uint32_t)__cvta_generic_to_shared(SCR);
    const float* W1c = W1 + 512*Dd;
    const float* s1Tsrc = g_s1T + b*16384;

    // ---- prologue cp.async: ST1T (G0), W1c tile0 (G1), tile1 (G2) ----
    #pragma unroll
    for (int u = 0; u < 8; u++){
        int off = u*8192 + tid*16;
        cp_async16(st1t_smem + off, (const char*)s1Tsrc + off);
    }
    CP_COMMIT();
    #pragma unroll
    for (int u = 0; u < 2; u++){
        int off = u*8192 + tid*16;
        cp_async16(scr_smem + off, (const char*)W1c + off);
    }
    CP_COMMIT();
    #pragma unroll
    for (int u = 0; u < 2; u++){
        int off = u*8192 + tid*16;
        cp_async16(scr_smem + 16384 + off, (const char*)W1c + 16384 + off);
    }
    CP_COMMIT();

    // ---- small fills ----
    if (tid < 256){
        float a = clip50(slots_t[(b*Nn + i)*Dd + tid]);
        STIPu[tid] = pack2(a, a);
        AB[tid] = g_A[(b*Nn + i)*Dd + tid];
    } else if (tid < 320){
        W3S[tid - 256] = W3[tid - 256];
    } else if (tid < 384){
        B2S[tid - 320] = b2[tid - 320];
    }

    const u64 NEG1 = 0xBF800000BF800000ULL;
    const u64 ABSM = 0x7FFFFFFF7FFFFFFFULL;

    CP_WAIT2();          // ST1T resident
    __syncthreads();     // STIP/AB visible

    // ---- DD(0): DD[kk][j] = (|a-s|,|a-s|) duplicated ----
    {
        const int kk = tid >> 5, jp = tid & 31;
        u64 s2 = ST1Tu[kk*32 + jp];
        u64 a2 = STIPu[kk];
        u64 dp = fma2r(s2, NEG1, a2) & ABSM;
        float dlo, dhi; unpack2(dp, dlo, dhi);
        DDu[kk*64 + 2*jp    ] = pack2(dlo, dlo);
        DDu[kk*64 + 2*jp + 1] = pack2(dhi, dhi);
    }

    // ---- GEMM1 mainloop (16 tiles of K=16) ----
    u64 acc[4][4];
    #pragma unroll
    for (int p=0;p<4;p++)
        #pragma unroll
        for (int q=0;q<4;q++) acc[p][q] = 0ULL;

    for (int t = 0; t < 16; t++){
        if (t < 15) { CP_WAIT1(); } else { CP_WAIT0(); }
        __syncthreads();

        // build DD(t+1) into other buffer
        if (t < 15){
            const int kk = tid >> 5, jp = tid & 31;
            u64* DDn = DDu + ((t+1)&1)*1024;
            u64 s2 = ST1Tu[((t+1)*16 + kk)*32 + jp];
            u64 a2 = STIPu[(t+1)*16 + kk];
            u64 dp = fma2r(s2, NEG1, a2) & ABSM;
            float dlo, dhi; unpack2(dp, dlo, dhi);
            DDn[kk*64 + 2*jp    ] = pack2(dlo, dlo);
            DDn[kk*64 + 2*jp + 1] = pack2(dhi, dhi);
        }

        const u64* WS  = SCRu + (t&1)*2048;   // [16][128] u64
        const u64* DDb = DDu  + (t&1)*1024;   // [16][64] u64

        #pragma unroll 16
        for (int kk = 0; kk < 16; kk++){
            u64 w0 = WS[kk*128 + tx];
            u64 w1 = WS[kk*128 + tx + 32];
            u64 w2 = WS[kk*128 + tx + 64];
            u64 w3 = WS[kk*128 + tx + 96];
            u64 d0 = DDb[kk*64 + jb + 0];
            u64 d1 = DDb[kk*64 + jb + 1];
            u64 d2 = DDb[kk*64 + jb + 2];
            u64 d3 = DDb[kk*64 + jb + 3];
            fma2(acc[0][0], d0, w0); fma2(acc[0][1], d0, w1);
            fma2(acc[0][2], d0, w2); fma2(acc[0][3], d0, w3);
            fma2(acc[1][0], d1, w0); fma2(acc[1][1], d1, w1);
            fma2(acc[1][2], d1, w2); fma2(acc[1][3], d1, w3);
            fma2(acc[2][0], d2, w0); fma2(acc[2][1], d2, w1);
            fma2(acc[2][2], d2, w2); fma2(acc[2][3], d2, w3);
            fma2(acc[3][0], d3, w0); fma2(acc[3][1], d3, w1);
            fma2(acc[3][2], d3, w2); fma2(acc[3][3], d3, w3);
        }
        __syncthreads();
        if (t + 2 < 16){
            const int tn = t + 2;
            #pragma unroll
            for (int u = 0; u < 2; u++){
                int off = u*8192 + tid*16;
                cp_async16(scr_smem + (tn&1)*16384 + off, (const char*)W1c + tn*16384 + off);
            }
            CP_COMMIT();
        }
    }

    // ---- GEMM1 epilogue: add A_i + (Bm_j + b1), relu, write H ----
    #pragma unroll
    for (int p=0;p<4;p++){
        const int j = jb + p;
        #pragma unroll
        for (int q=0;q<4;q++){
            const int cpair = tx + 32*q;
            float2 ab = *reinterpret_cast<const float2*>(&AB[2*cpair]);
            float2 bm = *reinterpret_cast<const float2*>(&g_Bm[(b*Nn + j)*Dd + 2*cpair]);
            float lo, hi; unpack2(acc[p][q], lo, hi);
            float2 hv = make_float2(fmaxf(lo + ab.x + bm.x, 0.f),
                                    fmaxf(hi + ab.y + bm.y, 0.f));
            *reinterpret_cast<float2*>(&H[j*256 + 2*cpair]) = hv;
        }
    }
    __syncthreads();   // H ready; ST1T fully dead (all DD built)

    // ---- build W2 pair layout in ST1T region: W2P[kp][m] = (W2[2kp][m], W2[2kp+1][m]) ----
    u64* W2P = ST1Tu;
    #pragma unroll
    for (int n = 0; n < 16; n++){
        int idx = tid + n*512;
        int kp = idx >> 6, m = idx & 63;
        W2P[idx] = pack2(W2[(2*kp)*64 + m], W2[(2*kp + 1)*64 + m]);
    }
    __syncthreads();

    // ---- GEMM2: H2 = relu(H @ W2 + b2); warp w owns rows w*4..w*4+3 ----
    u64 acc2[4][2];
    #pragma unroll
    for (int rr=0;rr<4;rr++){ acc2[rr][0]=0ULL; acc2[rr][1]=0ULL; }

    #pragma unroll 8
    for (int kp = 0; kp < 128; kp++){
        u64 wp0 = W2P[kp*64 + tx];
        u64 wp1 = W2P[kp*64 + 32 + tx];
        #pragma unroll
        for (int rr=0;rr<4;rr++){
            u64 hp = lds64(&H[(jb+rr)*256 + 2*kp]);
            fma2(acc2[rr][0], hp, wp0);
            fma2(acc2[rr][1], hp, wp1);
        }
    }
    __syncthreads();   // SCR fully dead; reuse as H2

    float* H2 = sm + SOFF_SCR;   // [64][64]
    #pragma unroll
    for (int rr=0;rr<4;rr++){
        float lo, hi;
        unpack2(acc2[rr][0], lo, hi);
        H2[(jb+rr)*64 + tx     ] = fmaxf(lo + hi + B2S[tx     ], 0.f);
        unpack2(acc2[rr][1], lo, hi);
        H2[(jb+rr)*64 + tx + 32] = fmaxf(lo + hi + B2S[tx + 32], 0.f);
    }
    __syncthreads();

    // ---- GEMM3 + penalties + log_alpha ----
    {
        const int g = tx >> 3, l = tx & 7;
        const int j = w*4 + g;
        float4 hA = *reinterpret_cast<const float4*>(&H2[j*64 + l*8]);
        float4 hB = *reinterpret_cast<const float4*>(&H2[j*64 + l*8 + 4]);
        float4 wA = *reinterpret_cast<const float4*>(&W3S[l*8]);
        float4 wB = *reinterpret_cast<const float4*>(&W3S[l*8 + 4]);
        float s = hA.x*wA.x + hA.y*wA.y + hA.z*wA.z + hA.w*wA.w
                + hB.x*wB.x + hB.y*wB.y + hB.z*wB.z + hB.w*wB.w;
        s += __shfl_xor_sync(0xffffffffu, s, 4);
        s += __shfl_xor_sync(0xffffffffu, s, 2);
        s += __shfl_xor_sync(0xffffffffu, s, 1);
        if (l == 0){
            float score = s + b3[0];
            if (alive_t [b*Nn + i] < 0.5f) score -= PEN;
            if (alive_t1[b*Nn + j] < 0.5f) score -= PEN;
            float la = fminf(fmaxf(score, -PEN), PEN) * INV_TEMP;
            g_la[(b*Nn + i)*Nn + j] = la;
        }
    }
}

// ================= Kernel 3: Sinkhorn (20 iters) + argmax + matched ==============
__global__ void __launch_bounds__(512) sinkhorn_kernel(
    const float* __restrict__ alive_t, const float* __restrict__ alive_t1,
    float* __restrict__ out)
{
    __shared__ float la[64][65];
    const int b = blockIdx.x;
    const int tid = threadIdx.x;
    const int lane = tid & 31, w = tid >> 5;   // 16 warps

    for (int idx = tid; idx < 64*64; idx += 512)
        la[idx >> 6][idx & 63] = g_la[b*4096 + idx];
    __syncthreads();

    for (int it = 0; it < 20; it++){
        #pragma unroll
        for (int rr = 0; rr < 4; rr++){
            const int i = w*4 + rr;
            float v0 = la[i][lane], v1 = la[i][lane+32];
            float m = fmaxf(v0, v1);
            #pragma unroll
            for (int off = 16; off > 0; off >>= 1) m = fmaxf(m, __shfl_xor_sync(0xffffffffu, m, off));
            float s = expf(v0 - m) + expf(v1 - m);
            #pragma unroll
            for (int off = 16; off > 0; off >>= 1) s += __shfl_xor_sync(0xffffffffu, s, off);
            float lse = m + logf(s);
            la[i][lane]    = v0 - lse;
            la[i][lane+32] = v1 - lse;
        }
        __syncthreads();
        #pragma unroll
        for (int rr = 0; rr < 4; rr++){
            const int j = w*4 + rr;
            float v0 = la[lane][j], v1 = la[lane+32][j];
            float m = fmaxf(v0, v1);
            #pragma unroll
            for (int off = 16; off > 0; off >>= 1) m = fmaxf(m, __shfl_xor_sync(0xffffffffu, m, off));
            float s = expf(v0 - m) + expf(v1 - m);
            #pragma unroll
            for (int off = 16; off > 0; off >>= 1) s += __shfl_xor_sync(0xffffffffu, s, off);
            float lse = m + logf(s);
            la[lane][j]    = v0 - lse;
            la[lane+32][j] = v1 - lse;
        }
        __syncthreads();
    }

    #pragma unroll
    for (int rr = 0; rr < 4; rr++){
        const int i = w*4 + rr;
        float v0 = la[i][lane], v1 = la[i][lane+32];
        float bv; int bi;
        if (v1 > v0){ bv = v1; bi = lane + 32; } else { bv = v0; bi = lane; }
        #pragma unroll
        for (int off = 16; off > 0; off >>= 1){
            float ov = __shfl_xor_sync(0xffffffffu, bv, off);
            int   oi = __shfl_xor_sync(0xffffffffu, bi, off);
            if (ov > bv || (ov == bv && oi < bi)){ bv = ov; bi = oi; }
        }
        if (lane == 0){
            float conf = expf(bv);
            float at  = alive_t [b*Nn + i];
            float at1 = alive_t1[b*Nn + bi];
            float matched = (at > 0.5f && at1 > 0.5f && conf > 0.3f) ? 1.f : 0.f;
            out[b*Nn + i]           = (float)bi;   // perm
            out[Bb*Nn + b*Nn + i]   = matched;     // matched
        }
    }
}

// ================= launch =================
extern "C" void kernel_launch(void* const* d_in, const int* in_sizes, int n_in,
                              void* d_out, int out_size)
{
    const float* slots_t  = (const float*)d_in[0];
    const float* slots_t1 = (const float*)d_in[1];
    const float* alive_t  = (const float*)d_in[2];
    const float* alive_t1 = (const float*)d_in[3];
    const float* W1 = (const float*)d_in[4];
    const float* b1 = (const float*)d_in[5];
    const float* W2 = (const float*)d_in[6];
    const float* b2 = (const float*)d_in[7];
    const float* W3 = (const float*)d_in[8];
    const float* b3 = (const float*)d_in[9];
    float* out = (float*)d_out;

    cudaFuncSetAttribute(precompute_kernel, cudaFuncAttributeMaxDynamicSharedMemorySize, P_SMEM_BYTES);
    cudaFuncSetAttribute(score_kernel,      cudaFuncAttributeMaxDynamicSharedMemorySize, S_SMEM_BYTES);

    precompute_kernel<<<dim3(4, Bb), 512, P_SMEM_BYTES>>>(slots_t, slots_t1, W1, b1);
    score_kernel<<<dim3(Nn, Bb), 512, S_SMEM_BYTES>>>(slots_t, alive_t, alive_t1,
                                                      W1, W2, b2, W3, b3);
    sinkhorn_kernel<<<Bb, 512>>>(alive_t, alive_t1, out);
}

// round 8
// speedup vs baseline: 1.5400x; 1.5400x over previous
#include <cuda_runtime.h>
#include <math.h>
#include <stdint.h>

#define Bb 32
#define Nn 64
#define Dd 256
#define PEN 10000.0f
#define INV_TEMP 20.0f

typedef unsigned long long u64;

// ---------------- device scratch ----------------
__device__ float g_A [Bb*Nn*Dd];
__device__ float g_Bm[Bb*Nn*Dd];
__device__ float g_la[Bb*Nn*Nn];
__device__ uint2 g_W1Fh[32*32*32];   // W1c fragment-packed hi: [ct][ks][lane] -> (B[k][c], B[k+4][c])
__device__ uint2 g_W1Fl[32*32*32];
__device__ uint2 g_W2Fh[8*32*32];
__device__ uint2 g_W2Fl[8*32*32];

__device__ __forceinline__ float clip50(float x){ return fminf(fmaxf(x, -50.f), 50.f); }
__device__ __forceinline__ uint32_t tf32bits(float x){
    uint32_t r; asm("cvt.rna.tf32.f32 %0, %1;" : "=r"(r) : "f"(x)); return r;
}
__device__ __forceinline__ void split_tf32(float x, uint32_t &h, uint32_t &l){
    h = tf32bits(x);
    l = tf32bits(x - __uint_as_float(h));
}
__device__ __forceinline__ void mma_tf32(float* d, const uint32_t* a, uint32_t b0, uint32_t b1){
    asm volatile("mma.sync.aligned.m16n8k8.row.col.f32.tf32.tf32.f32 "
        "{%0,%1,%2,%3}, {%4,%5,%6,%7}, {%8,%9}, {%0,%1,%2,%3};"
        : "+f"(d[0]), "+f"(d[1]), "+f"(d[2]), "+f"(d[3])
        : "r"(a[0]), "r"(a[1]), "r"(a[2]), "r"(a[3]), "r"(b0), "r"(b1));
}
__device__ __forceinline__ u64 pack2(float x, float y){
    u64 r; asm("mov.b64 %0, {%1, %2};" : "=l"(r) : "f"(x), "f"(y)); return r;
}
__device__ __forceinline__ void unpack2(u64 v, float &lo, float &hi){
    asm("mov.b64 {%0, %1}, %2;" : "=f"(lo), "=f"(hi) : "l"(v));
}
__device__ __forceinline__ void fma2(u64 &acc, u64 a, u64 b){
    asm("fma.rn.f32x2 %0, %1, %2, %0;" : "+l"(acc) : "l"(a), "l"(b));
}
__device__ __forceinline__ void cp_async16(uint32_t dst, const void* src){
    asm volatile("cp.async.ca.shared.global [%0], [%1], 16;" :: "r"(dst), "l"(src));
}
#define CP_COMMIT() asm volatile("cp.async.commit_group;")
#define CP_WAIT1()  asm volatile("cp.async.wait_group 1;")
#define CP_WAIT0()  asm volatile("cp.async.wait_group 0;")

// ============ Kernel 0: pack W1c / W2 into tf32 hi/lo fragment layouts ============
__global__ void __launch_bounds__(256) pack_weights(const float* __restrict__ W1,
                                                    const float* __restrict__ W2)
{
    int gid = blockIdx.x*256 + threadIdx.x;
    int lane = gid & 31;
    if (gid < 32768){
        int ks = (gid >> 5) & 31;
        int ct = gid >> 10;
        int k = ks*8 + (lane & 3), c = ct*8 + (lane >> 2);
        const float* W1c = W1 + 512*Dd;
        float v0 = W1c[k*Dd + c], v1 = W1c[(k+4)*Dd + c];
        uint32_t h0, l0, h1, l1;
        split_tf32(v0, h0, l0); split_tf32(v1, h1, l1);
        g_W1Fh[gid] = make_uint2(h0, h1);
        g_W1Fl[gid] = make_uint2(l0, l1);
    } else if (gid < 40960){
        int idx = gid - 32768;
        int ks = (idx >> 5) & 31;
        int ct = idx >> 10;
        int k = ks*8 + (lane & 3), n = ct*8 + (lane >> 2);
        float v0 = W2[k*64 + n], v1 = W2[(k+4)*64 + n];
        uint32_t h0, l0, h1, l1;
        split_tf32(v0, h0, l0); split_tf32(v1, h1, l1);
        g_W2Fh[idx] = make_uint2(h0, h1);
        g_W2Fl[idx] = make_uint2(l0, l1);
    }
}

// ============ Kernel 1: g_A = clip(s_t)@W1a ; g_Bm = clip(s_t1)@W1b + b1 ============
#define P_S0D 0
#define P_S1D 8704
#define P_WT  17408
#define P_SMEM_BYTES ((17408 + 32768)*4)

__global__ void __launch_bounds__(512, 1) precompute_kernel(
    const float* __restrict__ slots_t, const float* __restrict__ slots_t1,
    const float* __restrict__ W1, const float* __restrict__ b1)
{
    extern __shared__ float psm[];
    u64* S0D = reinterpret_cast<u64*>(psm + P_S0D);
    u64* S1D = reinterpret_cast<u64*>(psm + P_S1D);
    float* WT = psm + P_WT;
    const u64* WTu = reinterpret_cast<const u64*>(WT);
    const int ig = blockIdx.x, b = blockIdx.y;
    const int tid = threadIdx.x;
    const int rowbase = b*Nn + ig*16;
    const int gbase = rowbase * Dd;
    const uint32_t wt_smem = (uint32_t)__cvta_generic_to_shared(WT);

    #pragma unroll
    for (int t = 0; t < 2; t++){
        #pragma unroll
        for (int u = 0; u < 4; u++){
            int off = u*8192 + tid*16;
            cp_async16(wt_smem + t*65536 + off,         (const char*)(W1 + t*32*Dd) + off);
            cp_async16(wt_smem + t*65536 + 32768 + off, (const char*)(W1 + (256 + t*32)*Dd) + off);
        }
        CP_COMMIT();
    }
    #pragma unroll
    for (int n = 0; n < 8; n++){
        int idx = tid + n*512;
        int r = idx >> 8, k = idx & 255;
        float v0 = clip50(slots_t [gbase + idx]);
        float v1 = clip50(slots_t1[gbase + idx]);
        S0D[k*17 + r] = pack2(v0, v0);
        S1D[k*17 + r] = pack2(v1, v1);
    }
    __syncthreads();

    const int cp = tid & 127;
    const int rb = (tid >> 7) * 4;
    u64 accA[4], accB[4];
    #pragma unroll
    for (int p=0;p<4;p++){ accA[p]=0ULL; accB[p]=0ULL; }

    for (int t = 0; t < 8; t++){
        if (t < 7) { CP_WAIT1(); } else { CP_WAIT0(); }
        __syncthreads();
        const u64* WS = WTu + (t&1)*8192;
        #pragma unroll 8
        for (int kk = 0; kk < 32; kk++){
            const int k = t*32 + kk;
            u64 wA = WS[kk*128 + cp];
            u64 wB = WS[4096 + kk*128 + cp];
            #pragma unroll
            for (int p=0;p<4;p++){
                fma2(accA[p], S0D[k*17 + rb + p], wA);
                fma2(accB[p], S1D[k*17 + rb + p], wB);
            }
        }
        __syncthreads();
        if (t + 2 < 8){
            const int tn = t + 2;
            #pragma unroll
            for (int u = 0; u < 4; u++){
                int off = u*8192 + tid*16;
                cp_async16(wt_smem + (tn&1)*65536 + off,         (const char*)(W1 + tn*32*Dd) + off);
                cp_async16(wt_smem + (tn&1)*65536 + 32768 + off, (const char*)(W1 + (256 + tn*32)*Dd) + off);
            }
            CP_COMMIT();
        }
    }
    const float2 b1p = *reinterpret_cast<const float2*>(&b1[2*cp]);
    #pragma unroll
    for (int p=0;p<4;p++){
        float lo, hi;
        unpack2(accA[p], lo, hi);
        *reinterpret_cast<float2*>(&g_A[(rowbase + rb + p)*Dd + 2*cp]) = make_float2(lo, hi);
        unpack2(accB[p], lo, hi);
        *reinterpret_cast<float2*>(&g_Bm[(rowbase + rb + p)*Dd + 2*cp]) = make_float2(lo + b1p.x, hi + b1p.y);
    }
}

// ============ Kernel 2: tf32 tensor score kernel, CTA = (i, b) ============
#define ZOFF_S1  0                 // [64][260]
#define ZOFF_H   16640             // [64][260]
#define ZOFF_H2  33280             // [64][68]
#define ZOFF_STI 37632             // [256]
#define ZOFF_AB  37888             // [256]
#define ZOFF_B2  38144             // [64]
#define ZOFF_W3  38208             // [64]
#define Z_SMEM_BYTES (38272*4)     // 153088

__global__ void __launch_bounds__(512, 1) score_kernel(
    const float* __restrict__ slots_t, const float* __restrict__ slots_t1,
    const float* __restrict__ alive_t, const float* __restrict__ alive_t1,
    const float* __restrict__ b2, const float* __restrict__ W3,
    const float* __restrict__ b3)
{
    extern __shared__ float sm[];
    float* S1  = sm + ZOFF_S1;    // stride 260
    float* H   = sm + ZOFF_H;     // stride 260
    float* H2  = sm + ZOFF_H2;    // stride 68
    float* STI = sm + ZOFF_STI;
    float* AB  = sm + ZOFF_AB;
    float* B2S = sm + ZOFF_B2;
    float* W3S = sm + ZOFF_W3;

    const int i = blockIdx.x, b = blockIdx.y;
    const int tid = threadIdx.x;
    const int lane = tid & 31, w = tid >> 5;
    const int mtile = w & 3;          // j rows mtile*16 .. +15
    const int grp = w >> 2;           // GEMM1: c block grp*64; GEMM2: ntiles 2*grp..+1
    const int tg = lane & 3, gi = lane >> 2;

    // ---- fills ----
    if (tid < 256){
        STI[tid] = clip50(slots_t[(b*Nn + i)*Dd + tid]);
        AB[tid]  = g_A[(b*Nn + i)*Dd + tid];
    } else if (tid < 320){ B2S[tid-256] = b2[tid-256]; }
    else if (tid < 384){ W3S[tid-320] = W3[tid-320]; }
    for (int idx = tid; idx < Nn*Dd; idx += 512){
        int j = idx >> 8, k = idx & 255;
        S1[j*260 + k] = clip50(slots_t1[(b*Nn + j)*Dd + idx - (j<<8)]);
    }
    __syncthreads();

    // ---- GEMM1: D1[64j][256c] = |diff| @ W1c (3xTF32), acc in fp32 frags ----
    float acc[8][4];
    #pragma unroll
    for (int q=0;q<8;q++){ acc[q][0]=0.f; acc[q][1]=0.f; acc[q][2]=0.f; acc[q][3]=0.f; }

    const int j0 = mtile*16 + gi;
    for (int ks = 0; ks < 32; ks++){
        const int k0 = ks*8 + tg, k1 = k0 + 4;
        float t0 = STI[k0], t1 = STI[k1];
        float x0 = fabsf(t0 - S1[ j0   *260 + k0]);
        float x1 = fabsf(t0 - S1[(j0+8)*260 + k0]);
        float x2 = fabsf(t1 - S1[ j0   *260 + k1]);
        float x3 = fabsf(t1 - S1[(j0+8)*260 + k1]);
        uint32_t ah[4], al[4];
        split_tf32(x0, ah[0], al[0]); split_tf32(x1, ah[1], al[1]);
        split_tf32(x2, ah[2], al[2]); split_tf32(x3, ah[3], al[3]);
        const uint2* ph = g_W1Fh + ((grp*8)*32 + ks)*32 + lane;
        const uint2* pl = g_W1Fl + ((grp*8)*32 + ks)*32 + lane;
        #pragma unroll
        for (int q=0;q<8;q++){
            uint2 bh = ph[q*1024];     // (ct = grp*8+q): stride ct -> 32*32
            uint2 bl = pl[q*1024];
            mma_tf32(acc[q], ah, bh.x, bh.y);
            mma_tf32(acc[q], al, bh.x, bh.y);
            mma_tf32(acc[q], ah, bl.x, bl.y);
        }
    }

    // epilogue: H = relu(D1 + AB[c] + Bm[j][c])
    #pragma unroll
    for (int q=0;q<8;q++){
        const int c0 = (grp*8 + q)*8 + 2*tg;
        float2 ab = *reinterpret_cast<const float2*>(&AB[c0]);
        float2 bm0 = *reinterpret_cast<const float2*>(&g_Bm[(b*Nn + j0    )*Dd + c0]);
        float2 bm1 = *reinterpret_cast<const float2*>(&g_Bm[(b*Nn + j0 + 8)*Dd + c0]);
        float2 h0 = make_float2(fmaxf(acc[q][0] + ab.x + bm0.x, 0.f),
                                fmaxf(acc[q][1] + ab.y + bm0.y, 0.f));
        float2 h1 = make_float2(fmaxf(acc[q][2] + ab.x + bm1.x, 0.f),
                                fmaxf(acc[q][3] + ab.y + bm1.y, 0.f));
        *reinterpret_cast<float2*>(&H[ j0   *260 + c0]) = h0;
        *reinterpret_cast<float2*>(&H[(j0+8)*260 + c0]) = h1;
    }
    __syncthreads();

    // ---- GEMM2: D2[64j][64m] = H @ W2 (3xTF32) ----
    float acc2[2][4];
    #pragma unroll
    for (int t=0;t<2;t++){ acc2[t][0]=0.f; acc2[t][1]=0.f; acc2[t][2]=0.f; acc2[t][3]=0.f; }

    for (int ks = 0; ks < 32; ks++){
        const int k0 = ks*8 + tg, k1 = k0 + 4;
        float x0 = H[ j0   *260 + k0];
        float x1 = H[(j0+8)*260 + k0];
        float x2 = H[ j0   *260 + k1];
        float x3 = H[(j0+8)*260 + k1];
        uint32_t ah[4], al[4];
        split_tf32(x0, ah[0], al[0]); split_tf32(x1, ah[1], al[1]);
        split_tf32(x2, ah[2], al[2]); split_tf32(x3, ah[3], al[3]);
        #pragma unroll
        for (int t=0;t<2;t++){
            const int nt = 2*grp + t;
            uint2 bh = g_W2Fh[(nt*32 + ks)*32 + lane];
            uint2 bl = g_W2Fl[(nt*32 + ks)*32 + lane];
            mma_tf32(acc2[t], ah, bh.x, bh.y);
            mma_tf32(acc2[t], al, bh.x, bh.y);
            mma_tf32(acc2[t], ah, bl.x, bl.y);
        }
    }

    // epilogue: H2 = relu(D2 + b2)
    #pragma unroll
    for (int t=0;t<2;t++){
        const int m0 = (2*grp + t)*8 + 2*tg;
        float2 bb = *reinterpret_cast<const float2*>(&B2S[m0]);
        *reinterpret_cast<float2*>(&H2[ j0   *68 + m0]) =
            make_float2(fmaxf(acc2[t][0] + bb.x, 0.f), fmaxf(acc2[t][1] + bb.y, 0.f));
        *reinterpret_cast<float2*>(&H2[(j0+8)*68 + m0]) =
            make_float2(fmaxf(acc2[t][2] + bb.x, 0.f), fmaxf(acc2[t][3] + bb.y, 0.f));
    }
    __syncthreads();

    // ---- GEMM3 + penalties ----
    if (tid < 64){
        const int j = tid;
        float s0=0.f, s1=0.f, s2=0.f, s3=0.f;
        #pragma unroll
        for (int c = 0; c < 64; c += 4){
            s0 = fmaf(H2[j*68 + c  ], W3S[c  ], s0);
            s1 = fmaf(H2[j*68 + c+1], W3S[c+1], s1);
            s2 = fmaf(H2[j*68 + c+2], W3S[c+2], s2);
            s3 = fmaf(H2[j*68 + c+3], W3S[c+3], s3);
        }
        float score = (s0+s1)+(s2+s3) + b3[0];
        if (alive_t [b*Nn + i] < 0.5f) score -= PEN;
        if (alive_t1[b*Nn + j] < 0.5f) score -= PEN;
        float la = fminf(fmaxf(score, -PEN), PEN) * INV_TEMP;
        g_la[(b*Nn + i)*Nn + j] = la;
    }
}

// ============ Kernel 3: Sinkhorn + argmax + matched ============
__global__ void __launch_bounds__(512) sinkhorn_kernel(
    const float* __restrict__ alive_t, const float* __restrict__ alive_t1,
    float* __restrict__ out)
{
    __shared__ float la[64][65];
    const int b = blockIdx.x;
    const int tid = threadIdx.x;
    const int lane = tid & 31, w = tid >> 5;

    for (int idx = tid; idx < 64*64; idx += 512)
        la[idx >> 6][idx & 63] = g_la[b*4096 + idx];
    __syncthreads();

    for (int it = 0; it < 20; it++){
        #pragma unroll
        for (int rr = 0; rr < 4; rr++){
            const int i = w*4 + rr;
            float v0 = la[i][lane], v1 = la[i][lane+32];
            float m = fmaxf(v0, v1);
            #pragma unroll
            for (int off = 16; off > 0; off >>= 1) m = fmaxf(m, __shfl_xor_sync(0xffffffffu, m, off));
            float s = expf(v0 - m) + expf(v1 - m);
            #pragma unroll
            for (int off = 16; off > 0; off >>= 1) s += __shfl_xor_sync(0xffffffffu, s, off);
            float lse = m + logf(s);
            la[i][lane] = v0 - lse; la[i][lane+32] = v1 - lse;
        }
        __syncthreads();
        #pragma unroll
        for (int rr = 0; rr < 4; rr++){
            const int j = w*4 + rr;
            float v0 = la[lane][j], v1 = la[lane+32][j];
            float m = fmaxf(v0, v1);
            #pragma unroll
            for (int off = 16; off > 0; off >>= 1) m = fmaxf(m, __shfl_xor_sync(0xffffffffu, m, off));
            float s = expf(v0 - m) + expf(v1 - m);
            #pragma unroll
            for (int off = 16; off > 0; off >>= 1) s += __shfl_xor_sync(0xffffffffu, s, off);
            float lse = m + logf(s);
            la[lane][j] = v0 - lse; la[lane+32][j] = v1 - lse;
        }
        __syncthreads();
    }
    #pragma unroll
    for (int rr = 0; rr < 4; rr++){
        const int i = w*4 + rr;
        float v0 = la[i][lane], v1 = la[i][lane+32];
        float bv; int bi;
        if (v1 > v0){ bv = v1; bi = lane + 32; } else { bv = v0; bi = lane; }
        #pragma unroll
        for (int off = 16; off > 0; off >>= 1){
            float ov = __shfl_xor_sync(0xffffffffu, bv, off);
            int   oi = __shfl_xor_sync(0xffffffffu, bi, off);
            if (ov > bv || (ov == bv && oi < bi)){ bv = ov; bi = oi; }
        }
        if (lane == 0){
            float conf = expf(bv);
            float matched = (alive_t[b*Nn + i] > 0.5f && alive_t1[b*Nn + bi] > 0.5f && conf > 0.3f) ? 1.f : 0.f;
            out[b*Nn + i]         = (float)bi;
            out[Bb*Nn + b*Nn + i] = matched;
        }
    }
}

// ============ launch ============
extern "C" void kernel_launch(void* const* d_in, const int* in_sizes, int n_in,
                              void* d_out, int out_size)
{
    const float* slots_t  = (const float*)d_in[0];
    const float* slots_t1 = (const float*)d_in[1];
    const float* alive_t  = (const float*)d_in[2];
    const float* alive_t1 = (const float*)d_in[3];
    const float* W1 = (const float*)d_in[4];
    const float* b1 = (const float*)d_in[5];
    const float* W2 = (const float*)d_in[6];
    const float* b2 = (const float*)d_in[7];
    const float* W3 = (const float*)d_in[8];
    const float* b3 = (const float*)d_in[9];
    float* out = (float*)d_out;

    cudaFuncSetAttribute(precompute_kernel, cudaFuncAttributeMaxDynamicSharedMemorySize, P_SMEM_BYTES);
    cudaFuncSetAttribute(score_kernel,      cudaFuncAttributeMaxDynamicSharedMemorySize, Z_SMEM_BYTES);

    pack_weights<<<160, 256>>>(W1, W2);
    precompute_kernel<<<dim3(4, Bb), 512, P_SMEM_BYTES>>>(slots_t, slots_t1, W1, b1);
    score_kernel<<<dim3(Nn, Bb), 512, Z_SMEM_BYTES>>>(slots_t, slots_t1, alive_t, alive_t1,
                                                      b2, W3, b3);
    sinkhorn_kernel<<<Bb, 512>>>(alive_t, alive_t1, out);
}

// round 10
// speedup vs baseline: 1.7067x; 1.1083x over previous
#include <cuda_runtime.h>
#include <math.h>
#include <stdint.h>

#define Bb 32
#define Nn 64
#define Dd 256
#define PEN 10000.0f
#define INV_TEMP 20.0f

typedef unsigned long long u64;

__device__ float g_A [Bb*Nn*Dd];
__device__ float g_Bm[Bb*Nn*Dd];
__device__ float g_la[Bb*Nn*Nn];
__device__ uint2 g_W1Fh[32*32*32];
__device__ uint2 g_W1Fl[32*32*32];
__device__ uint2 g_W2Fh[8*32*32];
__device__ uint2 g_W2Fl[8*32*32];

__device__ __forceinline__ float clip50(float x){ return fminf(fmaxf(x, -50.f), 50.f); }
__device__ __forceinline__ uint32_t tf32bits(float x){
    uint32_t r; asm("cvt.rna.tf32.f32 %0, %1;" : "=r"(r) : "f"(x)); return r;
}
__device__ __forceinline__ void split_tf32(float x, uint32_t &h, uint32_t &l){
    h = tf32bits(x);
    l = tf32bits(x - __uint_as_float(h));
}
__device__ __forceinline__ void mma_tf32(float* d, const uint32_t* a, uint32_t b0, uint32_t b1){
    asm volatile("mma.sync.aligned.m16n8k8.row.col.f32.tf32.tf32.f32 "
        "{%0,%1,%2,%3}, {%4,%5,%6,%7}, {%8,%9}, {%0,%1,%2,%3};"
        : "+f"(d[0]), "+f"(d[1]), "+f"(d[2]), "+f"(d[3])
        : "r"(a[0]), "r"(a[1]), "r"(a[2]), "r"(a[3]), "r"(b0), "r"(b1));
}
__device__ __forceinline__ u64 pack2(float x, float y){
    u64 r; asm("mov.b64 %0, {%1, %2};" : "=l"(r) : "f"(x), "f"(y)); return r;
}
__device__ __forceinline__ void unpack2(u64 v, float &lo, float &hi){
    asm("mov.b64 {%0, %1}, %2;" : "=f"(lo), "=f"(hi) : "l"(v));
}
__device__ __forceinline__ void fma2(u64 &acc, u64 a, u64 b){
    asm("fma.rn.f32x2 %0, %1, %2, %0;" : "+l"(acc) : "l"(a), "l"(b));
}
__device__ __forceinline__ void cp_async16(uint32_t dst, const void* src){
    asm volatile("cp.async.ca.shared.global [%0], [%1], 16;" :: "r"(dst), "l"(src));
}
#define CP_COMMIT() asm volatile("cp.async.commit_group;")
#define CP_WAIT1()  asm volatile("cp.async.wait_group 1;")
#define CP_WAIT0()  asm volatile("cp.async.wait_group 0;")

// ============ Kernel 0: pack weights into tf32 hi/lo fragment layouts ============
__global__ void __launch_bounds__(256) pack_weights(const float* __restrict__ W1,
                                                    const float* __restrict__ W2)
{
    int gid = blockIdx.x*256 + threadIdx.x;
    int lane = gid & 31;
    if (gid < 32768){
        int ks = (gid >> 5) & 31;
        int ct = gid >> 10;
        int k = ks*8 + (lane & 3), c = ct*8 + (lane >> 2);
        const float* W1c = W1 + 512*Dd;
        float v0 = W1c[k*Dd + c], v1 = W1c[(k+4)*Dd + c];
        uint32_t h0, l0, h1, l1;
        split_tf32(v0, h0, l0); split_tf32(v1, h1, l1);
        g_W1Fh[gid] = make_uint2(h0, h1);
        g_W1Fl[gid] = make_uint2(l0, l1);
    } else if (gid < 40960){
        int idx = gid - 32768;
        int ks = (idx >> 5) & 31;
        int ct = idx >> 10;
        int k = ks*8 + (lane & 3), n = ct*8 + (lane >> 2);
        float v0 = W2[k*64 + n], v1 = W2[(k+4)*64 + n];
        uint32_t h0, l0, h1, l1;
        split_tf32(v0, h0, l0); split_tf32(v1, h1, l1);
        g_W2Fh[idx] = make_uint2(h0, h1);
        g_W2Fl[idx] = make_uint2(l0, l1);
    }
}

// ============ Kernel 1: g_A = clip(s_t)@W1a ; g_Bm = clip(s_t1)@W1b + b1 ============
#define P_S0D 0
#define P_S1D 8704
#define P_WT  17408
#define P_SMEM_BYTES ((17408 + 32768)*4)

__global__ void __launch_bounds__(512, 1) precompute_kernel(
    const float* __restrict__ slots_t, const float* __restrict__ slots_t1,
    const float* __restrict__ W1, const float* __restrict__ b1)
{
    extern __shared__ float psm[];
    u64* S0D = reinterpret_cast<u64*>(psm + P_S0D);
    u64* S1D = reinterpret_cast<u64*>(psm + P_S1D);
    float* WT = psm + P_WT;
    const u64* WTu = reinterpret_cast<const u64*>(WT);
    const int ig = blockIdx.x, b = blockIdx.y;
    const int tid = threadIdx.x;
    const int rowbase = b*Nn + ig*16;
    const int gbase = rowbase * Dd;
    const uint32_t wt_smem = (uint32_t)__cvta_generic_to_shared(WT);

    #pragma unroll
    for (int t = 0; t < 2; t++){
        #pragma unroll
        for (int u = 0; u < 4; u++){
            int off = u*8192 + tid*16;
            cp_async16(wt_smem + t*65536 + off,         (const char*)(W1 + t*32*Dd) + off);
            cp_async16(wt_smem + t*65536 + 32768 + off, (const char*)(W1 + (256 + t*32)*Dd) + off);
        }
        CP_COMMIT();
    }
    #pragma unroll
    for (int n = 0; n < 8; n++){
        int idx = tid + n*512;
        int r = idx >> 8, k = idx & 255;
        float v0 = clip50(slots_t [gbase + idx]);
        float v1 = clip50(slots_t1[gbase + idx]);
        S0D[k*17 + r] = pack2(v0, v0);
        S1D[k*17 + r] = pack2(v1, v1);
    }
    __syncthreads();

    const int cp = tid & 127;
    const int rb = (tid >> 7) * 4;
    u64 accA[4], accB[4];
    #pragma unroll
    for (int p=0;p<4;p++){ accA[p]=0ULL; accB[p]=0ULL; }

    for (int t = 0; t < 8; t++){
        if (t < 7) { CP_WAIT1(); } else { CP_WAIT0(); }
        __syncthreads();
        const u64* WS = WTu + (t&1)*8192;
        #pragma unroll 8
        for (int kk = 0; kk < 32; kk++){
            const int k = t*32 + kk;
            u64 wA = WS[kk*128 + cp];
            u64 wB = WS[4096 + kk*128 + cp];
            #pragma unroll
            for (int p=0;p<4;p++){
                fma2(accA[p], S0D[k*17 + rb + p], wA);
                fma2(accB[p], S1D[k*17 + rb + p], wB);
            }
        }
        __syncthreads();
        if (t + 2 < 8){
            const int tn = t + 2;
            #pragma unroll
            for (int u = 0; u < 4; u++){
                int off = u*8192 + tid*16;
                cp_async16(wt_smem + (tn&1)*65536 + off,         (const char*)(W1 + tn*32*Dd) + off);
                cp_async16(wt_smem + (tn&1)*65536 + 32768 + off, (const char*)(W1 + (256 + tn*32)*Dd) + off);
            }
            CP_COMMIT();
        }
    }
    const float2 b1p = *reinterpret_cast<const float2*>(&b1[2*cp]);
    #pragma unroll
    for (int p=0;p<4;p++){
        float lo, hi;
        unpack2(accA[p], lo, hi);
        *reinterpret_cast<float2*>(&g_A[(rowbase + rb + p)*Dd + 2*cp]) = make_float2(lo, hi);
        unpack2(accB[p], lo, hi);
        *reinterpret_cast<float2*>(&g_Bm[(rowbase + rb + p)*Dd + 2*cp]) = make_float2(lo + b1p.x, hi + b1p.y);
    }
}

// ============ Kernel 2: tf32 tensor score kernel, CTA = (i-pair, b), M=128 ============
// smem plan (floats): S1 [64][260] (later overlaid by H2 [128][68]); H [128][260]
#define ZOFF_S1  0                 // 16640 floats
#define ZOFF_H   16640             // 33280 floats
#define ZOFF_STI 49920             // [2][256]
#define ZOFF_AB  50432             // [2][256]
#define ZOFF_B2  50944             // [64]
#define ZOFF_W3  51008             // [64]
#define Z_SMEM_BYTES (51072*4)     // 204288

__global__ void __launch_bounds__(512, 1) score_kernel(
    const float* __restrict__ slots_t, const float* __restrict__ slots_t1,
    const float* __restrict__ alive_t, const float* __restrict__ alive_t1,
    const float* __restrict__ b2, const float* __restrict__ W3,
    const float* __restrict__ b3)
{
    extern __shared__ float sm[];
    float* S1  = sm + ZOFF_S1;    // stride 260
    float* H   = sm + ZOFF_H;     // stride 260
    float* H2  = sm + ZOFF_S1;    // overlays S1 after GEMM1; stride 68
    float* STI = sm + ZOFF_STI;
    float* AB  = sm + ZOFF_AB;
    float* B2S = sm + ZOFF_B2;
    float* W3S = sm + ZOFF_W3;

    const int i0 = blockIdx.x*2, b = blockIdx.y;
    const int tid = threadIdx.x;
    const int lane = tid & 31, w = tid >> 5;
    const int mt = w & 7;             // row tile: rows mt*16 .. +15 (of 128)
    const int cgrp = w >> 3;          // GEMM1: cols cgrp*128..+127
    const int tg = lane & 3, gi = lane >> 2;

    // ---- fills ----
    {
        int ii = tid >> 8, k = tid & 255;
        STI[tid] = clip50(slots_t[(b*Nn + i0 + ii)*Dd + k]);
        AB[tid]  = g_A[(b*Nn + i0 + ii)*Dd + k];
    }
    if (tid < 64){ B2S[tid] = b2[tid]; }
    else if (tid < 128){ W3S[tid-64] = W3[tid-64]; }
    for (int idx = tid; idx < Nn*Dd; idx += 512){
        int j = idx >> 8, k = idx & 255;
        S1[j*260 + k] = clip50(slots_t1[(b*Nn + j)*Dd + k]);
    }
    __syncthreads();

    const int r0 = mt*16 + gi;        // rows r0, r0+8
    const int ii = mt >> 2;           // which i of the pair
    const int jj = r0 & 63;           // j index

    // ---- GEMM1: D1[128r][256c] = |diff| @ W1c (3xTF32) ----
    float acc[16][4];
    #pragma unroll
    for (int q=0;q<16;q++){ acc[q][0]=0.f; acc[q][1]=0.f; acc[q][2]=0.f; acc[q][3]=0.f; }

    for (int ks = 0; ks < 32; ks++){
        const int k0 = ks*8 + tg, k1 = k0 + 4;
        float t0 = STI[ii*256 + k0], t1 = STI[ii*256 + k1];
        float x0 = fabsf(t0 - S1[ jj   *260 + k0]);
        float x1 = fabsf(t0 - S1[(jj+8)*260 + k0]);
        float x2 = fabsf(t1 - S1[ jj   *260 + k1]);
        float x3 = fabsf(t1 - S1[(jj+8)*260 + k1]);
        uint32_t ah[4], al[4];
        split_tf32(x0, ah[0], al[0]); split_tf32(x1, ah[1], al[1]);
        split_tf32(x2, ah[2], al[2]); split_tf32(x3, ah[3], al[3]);
        const uint2* ph = g_W1Fh + ((cgrp*16)*32 + ks)*32 + lane;
        const uint2* pl = g_W1Fl + ((cgrp*16)*32 + ks)*32 + lane;
        #pragma unroll
        for (int q=0;q<16;q++){
            uint2 bh = ph[q*1024];
            uint2 bl = pl[q*1024];
            mma_tf32(acc[q], ah, bh.x, bh.y);
            mma_tf32(acc[q], al, bh.x, bh.y);
            mma_tf32(acc[q], ah, bl.x, bl.y);
        }
    }

    // epilogue: H = relu(D1 + AB[ii][c] + Bm[jj][c])
    #pragma unroll
    for (int q=0;q<16;q++){
        const int c0 = (cgrp*16 + q)*8 + 2*tg;
        float2 ab = *reinterpret_cast<const float2*>(&AB[ii*256 + c0]);
        float2 bm0 = *reinterpret_cast<const float2*>(&g_Bm[(b*Nn + jj    )*Dd + c0]);
        float2 bm1 = *reinterpret_cast<const float2*>(&g_Bm[(b*Nn + jj + 8)*Dd + c0]);
        *reinterpret_cast<float2*>(&H[ r0   *260 + c0]) =
            make_float2(fmaxf(acc[q][0] + ab.x + bm0.x, 0.f), fmaxf(acc[q][1] + ab.y + bm0.y, 0.f));
        *reinterpret_cast<float2*>(&H[(r0+8)*260 + c0]) =
            make_float2(fmaxf(acc[q][2] + ab.x + bm1.x, 0.f), fmaxf(acc[q][3] + ab.y + bm1.y, 0.f));
    }
    __syncthreads();   // H ready; S1 dead from here (H2 overlays it)

    // ---- GEMM2: D2[128r][64m] = H @ W2 (3xTF32) ----
    float acc2[4][4];
    #pragma unroll
    for (int q=0;q<4;q++){ acc2[q][0]=0.f; acc2[q][1]=0.f; acc2[q][2]=0.f; acc2[q][3]=0.f; }

    for (int ks = 0; ks < 32; ks++){
        const int k0 = ks*8 + tg, k1 = k0 + 4;
        float x0 = H[ r0   *260 + k0];
        float x1 = H[(r0+8)*260 + k0];
        float x2 = H[ r0   *260 + k1];
        float x3 = H[(r0+8)*260 + k1];
        uint32_t ah[4], al[4];
        split_tf32(x0, ah[0], al[0]); split_tf32(x1, ah[1], al[1]);
        split_tf32(x2, ah[2], al[2]); split_tf32(x3, ah[3], al[3]);
        #pragma unroll
        for (int q=0;q<4;q++){
            const int nt = cgrp*4 + q;
            uint2 bh = g_W2Fh[(nt*32 + ks)*32 + lane];
            uint2 bl = g_W2Fl[(nt*32 + ks)*32 + lane];
            mma_tf32(acc2[q], ah, bh.x, bh.y);
            mma_tf32(acc2[q], al, bh.x, bh.y);
            mma_tf32(acc2[q], ah, bl.x, bl.y);
        }
    }
    __syncthreads();   // all H2-region (old S1) reads done before overwrite

    #pragma unroll
    for (int q=0;q<4;q++){
        const int m0 = (cgrp*4 + q)*8 + 2*tg;
        float2 bb = *reinterpret_cast<const float2*>(&B2S[m0]);
        *reinterpret_cast<float2*>(&H2[ r0   *68 + m0]) =
            make_float2(fmaxf(acc2[q][0] + bb.x, 0.f), fmaxf(acc2[q][1] + bb.y, 0.f));
        *reinterpret_cast<float2*>(&H2[(r0+8)*68 + m0]) =
            make_float2(fmaxf(acc2[q][2] + bb.x, 0.f), fmaxf(acc2[q][3] + bb.y, 0.f));
    }
    __syncthreads();

    // ---- GEMM3 + penalties ----
    if (tid < 128){
        const int row = tid, i2 = row >> 6, j = row & 63;
        float s0=0.f, s1=0.f, s2=0.f, s3=0.f;
        #pragma unroll
        for (int c = 0; c < 64; c += 4){
            s0 = fmaf(H2[row*68 + c  ], W3S[c  ], s0);
            s1 = fmaf(H2[row*68 + c+1], W3S[c+1], s1);
            s2 = fmaf(H2[row*68 + c+2], W3S[c+2], s2);
            s3 = fmaf(H2[row*68 + c+3], W3S[c+3], s3);
        }
        float score = (s0+s1)+(s2+s3) + b3[0];
        if (alive_t [b*Nn + i0 + i2] < 0.5f) score -= PEN;
        if (alive_t1[b*Nn + j] < 0.5f) score -= PEN;
        float la = fminf(fmaxf(score, -PEN), PEN) * INV_TEMP;
        g_la[(b*Nn + i0 + i2)*Nn + j] = la;
    }
}

// ============ Kernel 3: Sinkhorn + argmax + matched (fast-math MUFU) ============
__global__ void __launch_bounds__(512) sinkhorn_kernel(
    const float* __restrict__ alive_t, const float* __restrict__ alive_t1,
    float* __restrict__ out)
{
    __shared__ float la[64][65];
    const int b = blockIdx.x;
    const int tid = threadIdx.x;
    const int lane = tid & 31, w = tid >> 5;

    for (int idx = tid; idx < 64*64; idx += 512)
        la[idx >> 6][idx & 63] = g_la[b*4096 + idx];
    __syncthreads();

    for (int it = 0; it < 20; it++){
        #pragma unroll
        for (int rr = 0; rr < 4; rr++){
            const int i = w*4 + rr;
            float v0 = la[i][lane], v1 = la[i][lane+32];
            float m = fmaxf(v0, v1);
            #pragma unroll
            for (int off = 16; off > 0; off >>= 1) m = fmaxf(m, __shfl_xor_sync(0xffffffffu, m, off));
            float s = __expf(v0 - m) + __expf(v1 - m);
            #pragma unroll
            for (int off = 16; off > 0; off >>= 1) s += __shfl_xor_sync(0xffffffffu, s, off);
            float lse = m + __logf(s);
            la[i][lane] = v0 - lse; la[i][lane+32] = v1 - lse;
        }
        __syncthreads();
        #pragma unroll
        for (int rr = 0; rr < 4; rr++){
            const int j = w*4 + rr;
            float v0 = la[lane][j], v1 = la[lane+32][j];
            float m = fmaxf(v0, v1);
            #pragma unroll
            for (int off = 16; off > 0; off >>= 1) m = fmaxf(m, __shfl_xor_sync(0xffffffffu, m, off));
            float s = __expf(v0 - m) + __expf(v1 - m);
            #pragma unroll
            for (int off = 16; off > 0; off >>= 1) s += __shfl_xor_sync(0xffffffffu, s, off);
            float lse = m + __logf(s);
            la[lane][j] = v0 - lse; la[lane+32][j] = v1 - lse;
        }
        __syncthreads();
    }
    #pragma unroll
    for (int rr = 0; rr < 4; rr++){
        const int i = w*4 + rr;
        float v0 = la[i][lane], v1 = la[i][lane+32];
        float bv; int bi;
        if (v1 > v0){ bv = v1; bi = lane + 32; } else { bv = v0; bi = lane; }
        #pragma unroll
        for (int off = 16; off > 0; off >>= 1){
            float ov = __shfl_xor_sync(0xffffffffu, bv, off);
            int   oi = __shfl_xor_sync(0xffffffffu, bi, off);
            if (ov > bv || (ov == bv && oi < bi)){ bv = ov; bi = oi; }
        }
        if (lane == 0){
            float conf = __expf(bv);
            float matched = (alive_t[b*Nn + i] > 0.5f && alive_t1[b*Nn + bi] > 0.5f && conf > 0.3f) ? 1.f : 0.f;
            out[b*Nn + i]         = (float)bi;
            out[Bb*Nn + b*Nn + i] = matched;
        }
    }
}

// ============ launch ============
extern "C" void kernel_launch(void* const* d_in, const int* in_sizes, int n_in,
                              void* d_out, int out_size)
{
    const float* slots_t  = (const float*)d_in[0];
    const float* slots_t1 = (const float*)d_in[1];
    const float* alive_t  = (const float*)d_in[2];
    const float* alive_t1 = (const float*)d_in[3];
    const float* W1 = (const float*)d_in[4];
    const float* b1 = (const float*)d_in[5];
    const float* W2 = (const float*)d_in[6];
    const float* b2 = (const float*)d_in[7];
    const float* W3 = (const float*)d_in[8];
    const float* b3 = (const float*)d_in[9];
    float* out = (float*)d_out;

    cudaFuncSetAttribute(precompute_kernel, cudaFuncAttributeMaxDynamicSharedMemorySize, P_SMEM_BYTES);
    cudaFuncSetAttribute(score_kernel,      cudaFuncAttributeMaxDynamicSharedMemorySize, Z_SMEM_BYTES);

    pack_weights<<<160, 256>>>(W1, W2);
    precompute_kernel<<<dim3(4, Bb), 512, P_SMEM_BYTES>>>(slots_t, slots_t1, W1, b1);
    score_kernel<<<dim3(Nn/2, Bb), 512, Z_SMEM_BYTES>>>(slots_t, slots_t1, alive_t, alive_t1,
                                                        b2, W3, b3);
    sinkhorn_kernel<<<Bb, 512>>>(alive_t, alive_t1, out);
}

// round 11
// speedup vs baseline: 2.4087x; 1.4113x over previous
#include <cuda_runtime.h>
#include <math.h>
#include <stdint.h>

#define Bb 32
#define Nn 64
#define Dd 256
#define PEN 10000.0f
#define INV_TEMP 20.0f

typedef unsigned long long u64;

__device__ float g_A [Bb*Nn*Dd];
__device__ float g_Bm[Bb*Nn*Dd];
__device__ float g_la[Bb*Nn*Nn];
__device__ uint2 g_W1Bh[32*16*32];   // W1c bf16-hi fragments [ct][ks][lane]
__device__ uint2 g_W1Bm[32*16*32];   // W1c bf16-mid fragments
__device__ uint2 g_W2Bh[8*16*32];
__device__ uint2 g_W2Bm[8*16*32];

__device__ __forceinline__ float clip50(float x){ return fminf(fmaxf(x, -50.f), 50.f); }
__device__ __forceinline__ uint32_t pkbf(float lo, float hi){
    uint32_t r; asm("cvt.rn.bf16x2.f32 %0, %1, %2;" : "=r"(r) : "f"(hi), "f"(lo)); return r;
}
// split pair into bf16x2 hi + bf16x2 mid (h recovered exactly via bit ops)
__device__ __forceinline__ void split_pair(float x0, float x1, uint32_t &h, uint32_t &m){
    h = pkbf(x0, x1);
    float h0 = __uint_as_float(h << 16);
    float h1 = __uint_as_float(h & 0xFFFF0000u);
    m = pkbf(x0 - h0, x1 - h1);
}
__device__ __forceinline__ void mma_bf16(float* d, const uint32_t* a, uint32_t b0, uint32_t b1){
    asm volatile("mma.sync.aligned.m16n8k16.row.col.f32.bf16.bf16.f32 "
        "{%0,%1,%2,%3}, {%4,%5,%6,%7}, {%8,%9}, {%0,%1,%2,%3};"
        : "+f"(d[0]), "+f"(d[1]), "+f"(d[2]), "+f"(d[3])
        : "r"(a[0]), "r"(a[1]), "r"(a[2]), "r"(a[3]), "r"(b0), "r"(b1));
}
__device__ __forceinline__ u64 pack2(float x, float y){
    u64 r; asm("mov.b64 %0, {%1, %2};" : "=l"(r) : "f"(x), "f"(y)); return r;
}
__device__ __forceinline__ void unpack2(u64 v, float &lo, float &hi){
    asm("mov.b64 {%0, %1}, %2;" : "=f"(lo), "=f"(hi) : "l"(v));
}
__device__ __forceinline__ void fma2(u64 &acc, u64 a, u64 b){
    asm("fma.rn.f32x2 %0, %1, %2, %0;" : "+l"(acc) : "l"(a), "l"(b));
}
__device__ __forceinline__ void cp_async16(uint32_t dst, const void* src){
    asm volatile("cp.async.ca.shared.global [%0], [%1], 16;" :: "r"(dst), "l"(src));
}
#define CP_COMMIT() asm volatile("cp.async.commit_group;")
#define CP_WAIT1()  asm volatile("cp.async.wait_group 1;")
#define CP_WAIT0()  asm volatile("cp.async.wait_group 0;")

// ============ Kernel 0: pack weights into bf16 hi/mid m16n8k16 B-fragments ============
// B-frag (col-major 16x8): b0 = (k0,k0+1 ; n), b1 = (k0+8,k0+9 ; n), k0=(lane&3)*2, n=lane>>2
__global__ void __launch_bounds__(256) pack_weights(const float* __restrict__ W1,
                                                    const float* __restrict__ W2)
{
    int gid = blockIdx.x*256 + threadIdx.x;
    int lane = gid & 31;
    if (gid < 16384){
        int ks = (gid >> 5) & 15;
        int ct = gid >> 9;
        int k0 = ks*16 + (lane & 3)*2, n = ct*8 + (lane >> 2);
        const float* W1c = W1 + 512*Dd;
        float v00 = W1c[ k0   *Dd + n], v01 = W1c[(k0+1)*Dd + n];
        float v10 = W1c[(k0+8)*Dd + n], v11 = W1c[(k0+9)*Dd + n];
        uint32_t b0h, b0m, b1h, b1m;
        split_pair(v00, v01, b0h, b0m);
        split_pair(v10, v11, b1h, b1m);
        g_W1Bh[gid] = make_uint2(b0h, b1h);
        g_W1Bm[gid] = make_uint2(b0m, b1m);
    } else if (gid < 20480){
        int idx = gid - 16384;
        int ks = (idx >> 5) & 15;
        int ct = idx >> 9;
        int k0 = ks*16 + (lane & 3)*2, n = ct*8 + (lane >> 2);
        float v00 = W2[ k0   *64 + n], v01 = W2[(k0+1)*64 + n];
        float v10 = W2[(k0+8)*64 + n], v11 = W2[(k0+9)*64 + n];
        uint32_t b0h, b0m, b1h, b1m;
        split_pair(v00, v01, b0h, b0m);
        split_pair(v10, v11, b1h, b1m);
        g_W2Bh[idx] = make_uint2(b0h, b1h);
        g_W2Bm[idx] = make_uint2(b0m, b1m);
    }
}

// ============ Kernel 1: g_A = clip(s_t)@W1a ; g_Bm = clip(s_t1)@W1b + b1 ============
#define P_S0D 0
#define P_S1D 8704
#define P_WT  17408
#define P_SMEM_BYTES ((17408 + 32768)*4)

__global__ void __launch_bounds__(512, 1) precompute_kernel(
    const float* __restrict__ slots_t, const float* __restrict__ slots_t1,
    const float* __restrict__ W1, const float* __restrict__ b1)
{
    extern __shared__ float psm[];
    u64* S0D = reinterpret_cast<u64*>(psm + P_S0D);
    u64* S1D = reinterpret_cast<u64*>(psm + P_S1D);
    float* WT = psm + P_WT;
    const u64* WTu = reinterpret_cast<const u64*>(WT);
    const int ig = blockIdx.x, b = blockIdx.y;
    const int tid = threadIdx.x;
    const int rowbase = b*Nn + ig*16;
    const int gbase = rowbase * Dd;
    const uint32_t wt_smem = (uint32_t)__cvta_generic_to_shared(WT);

    #pragma unroll
    for (int t = 0; t < 2; t++){
        #pragma unroll
        for (int u = 0; u < 4; u++){
            int off = u*8192 + tid*16;
            cp_async16(wt_smem + t*65536 + off,         (const char*)(W1 + t*32*Dd) + off);
            cp_async16(wt_smem + t*65536 + 32768 + off, (const char*)(W1 + (256 + t*32)*Dd) + off);
        }
        CP_COMMIT();
    }
    #pragma unroll
    for (int n = 0; n < 8; n++){
        int idx = tid + n*512;
        int r = idx >> 8, k = idx & 255;
        float v0 = clip50(slots_t [gbase + idx]);
        float v1 = clip50(slots_t1[gbase + idx]);
        S0D[k*17 + r] = pack2(v0, v0);
        S1D[k*17 + r] = pack2(v1, v1);
    }
    __syncthreads();

    const int cp = tid & 127;
    const int rb = (tid >> 7) * 4;
    u64 accA[4], accB[4];
    #pragma unroll
    for (int p=0;p<4;p++){ accA[p]=0ULL; accB[p]=0ULL; }

    for (int t = 0; t < 8; t++){
        if (t < 7) { CP_WAIT1(); } else { CP_WAIT0(); }
        __syncthreads();
        const u64* WS = WTu + (t&1)*8192;
        #pragma unroll 8
        for (int kk = 0; kk < 32; kk++){
            const int k = t*32 + kk;
            u64 wA = WS[kk*128 + cp];
            u64 wB = WS[4096 + kk*128 + cp];
            #pragma unroll
            for (int p=0;p<4;p++){
                fma2(accA[p], S0D[k*17 + rb + p], wA);
                fma2(accB[p], S1D[k*17 + rb + p], wB);
            }
        }
        __syncthreads();
        if (t + 2 < 8){
            const int tn = t + 2;
            #pragma unroll
            for (int u = 0; u < 4; u++){
                int off = u*8192 + tid*16;
                cp_async16(wt_smem + (tn&1)*65536 + off,         (const char*)(W1 + tn*32*Dd) + off);
                cp_async16(wt_smem + (tn&1)*65536 + 32768 + off, (const char*)(W1 + (256 + tn*32)*Dd) + off);
            }
            CP_COMMIT();
        }
    }
    const float2 b1p = *reinterpret_cast<const float2*>(&b1[2*cp]);
    #pragma unroll
    for (int p=0;p<4;p++){
        float lo, hi;
        unpack2(accA[p], lo, hi);
        *reinterpret_cast<float2*>(&g_A[(rowbase + rb + p)*Dd + 2*cp]) = make_float2(lo, hi);
        unpack2(accB[p], lo, hi);
        *reinterpret_cast<float2*>(&g_Bm[(rowbase + rb + p)*Dd + 2*cp]) = make_float2(lo + b1p.x, hi + b1p.y);
    }
}

// ============ Kernel 2: bf16 tensor score kernel, CTA = (i-pair, b), M=128 ============
#define ZOFF_S1  0                 // [64][260]; overlaid by H2 [128][68] after GEMM1
#define ZOFF_H   16640             // [128][260]
#define ZOFF_STI 49920             // [2][256]
#define ZOFF_AB  50432             // [2][256]
#define ZOFF_B2  50944             // [64]
#define ZOFF_W3  51008             // [64]
#define Z_SMEM_BYTES (51072*4)     // 204288

__global__ void __launch_bounds__(512, 1) score_kernel(
    const float* __restrict__ slots_t, const float* __restrict__ slots_t1,
    const float* __restrict__ alive_t, const float* __restrict__ alive_t1,
    const float* __restrict__ b2, const float* __restrict__ W3,
    const float* __restrict__ b3)
{
    extern __shared__ float sm[];
    float* S1  = sm + ZOFF_S1;    // stride 260
    float* H   = sm + ZOFF_H;     // stride 260
    float* H2  = sm + ZOFF_S1;    // overlays S1 after GEMM1; stride 68
    float* STI = sm + ZOFF_STI;
    float* AB  = sm + ZOFF_AB;
    float* B2S = sm + ZOFF_B2;
    float* W3S = sm + ZOFF_W3;

    const int i0 = blockIdx.x*2, b = blockIdx.y;
    const int tid = threadIdx.x;
    const int lane = tid & 31, w = tid >> 5;
    const int mt = w & 7;             // rows mt*16 .. +15 (of 128)
    const int cgrp = w >> 3;          // GEMM1: cols cgrp*128..+127
    const int tg = lane & 3, gi = lane >> 2;

    // ---- fills ----
    {
        int ii = tid >> 8, k = tid & 255;
        STI[tid] = clip50(slots_t[(b*Nn + i0 + ii)*Dd + k]);
        AB[tid]  = g_A[(b*Nn + i0 + ii)*Dd + k];
    }
    if (tid < 64){ B2S[tid] = b2[tid]; }
    else if (tid < 128){ W3S[tid-64] = W3[tid-64]; }
    for (int idx = tid; idx < Nn*Dd; idx += 512){
        int j = idx >> 8, k = idx & 255;
        S1[j*260 + k] = clip50(slots_t1[(b*Nn + j)*Dd + k]);
    }
    __syncthreads();

    const int r0 = mt*16 + gi;        // rows r0, r0+8
    const int ii = mt >> 2;
    const int jj = r0 & 63;

    // ---- GEMM1: D1[128r][256c] = |diff| @ W1c  (3xBF16, m16n8k16) ----
    float acc[16][4];
    #pragma unroll
    for (int q=0;q<16;q++){ acc[q][0]=0.f; acc[q][1]=0.f; acc[q][2]=0.f; acc[q][3]=0.f; }

    for (int ks = 0; ks < 16; ks++){
        const int kA = ks*16 + tg*2, kB = kA + 8;
        float2 tA = *reinterpret_cast<const float2*>(&STI[ii*256 + kA]);
        float2 tB = *reinterpret_cast<const float2*>(&STI[ii*256 + kB]);
        float2 sA0 = *reinterpret_cast<const float2*>(&S1[ jj   *260 + kA]);
        float2 sA1 = *reinterpret_cast<const float2*>(&S1[(jj+8)*260 + kA]);
        float2 sB0 = *reinterpret_cast<const float2*>(&S1[ jj   *260 + kB]);
        float2 sB1 = *reinterpret_cast<const float2*>(&S1[(jj+8)*260 + kB]);
        uint32_t ah[4], am[4];
        split_pair(fabsf(tA.x - sA0.x), fabsf(tA.y - sA0.y), ah[0], am[0]);
        split_pair(fabsf(tA.x - sA1.x), fabsf(tA.y - sA1.y), ah[1], am[1]);
        split_pair(fabsf(tB.x - sB0.x), fabsf(tB.y - sB0.y), ah[2], am[2]);
        split_pair(fabsf(tB.x - sB1.x), fabsf(tB.y - sB1.y), ah[3], am[3]);
        const uint2* pBh = g_W1Bh + (cgrp*16)*512 + ks*32 + lane;
        const uint2* pBm = g_W1Bm + (cgrp*16)*512 + ks*32 + lane;
        #pragma unroll
        for (int q=0;q<16;q++){
            uint2 bh = pBh[q*512];
            uint2 bm = pBm[q*512];
            mma_bf16(acc[q], ah, bh.x, bh.y);
            mma_bf16(acc[q], ah, bm.x, bm.y);
            mma_bf16(acc[q], am, bh.x, bh.y);
        }
    }

    // epilogue: H = relu(D1 + AB[ii][c] + Bm[jj][c])
    #pragma unroll
    for (int q=0;q<16;q++){
        const int c0 = (cgrp*16 + q)*8 + 2*tg;
        float2 ab = *reinterpret_cast<const float2*>(&AB[ii*256 + c0]);
        float2 bm0 = *reinterpret_cast<const float2*>(&g_Bm[(b*Nn + jj    )*Dd + c0]);
        float2 bm1 = *reinterpret_cast<const float2*>(&g_Bm[(b*Nn + jj + 8)*Dd + c0]);
        *reinterpret_cast<float2*>(&H[ r0   *260 + c0]) =
            make_float2(fmaxf(acc[q][0] + ab.x + bm0.x, 0.f), fmaxf(acc[q][1] + ab.y + bm0.y, 0.f));
        *reinterpret_cast<float2*>(&H[(r0+8)*260 + c0]) =
            make_float2(fmaxf(acc[q][2] + ab.x + bm1.x, 0.f), fmaxf(acc[q][3] + ab.y + bm1.y, 0.f));
    }
    __syncthreads();   // H ready; S1 dead from here

    // ---- GEMM2: D2[128r][64m] = H @ W2  (3xBF16) ----
    float acc2[4][4];
    #pragma unroll
    for (int q=0;q<4;q++){ acc2[q][0]=0.f; acc2[q][1]=0.f; acc2[q][2]=0.f; acc2[q][3]=0.f; }

    for (int ks = 0; ks < 16; ks++){
        const int kA = ks*16 + tg*2, kB = kA + 8;
        float2 hA0 = *reinterpret_cast<const float2*>(&H[ r0   *260 + kA]);
        float2 hA1 = *reinterpret_cast<const float2*>(&H[(r0+8)*260 + kA]);
        float2 hB0 = *reinterpret_cast<const float2*>(&H[ r0   *260 + kB]);
        float2 hB1 = *reinterpret_cast<const float2*>(&H[(r0+8)*260 + kB]);
        uint32_t ah[4], am[4];
        split_pair(hA0.x, hA0.y, ah[0], am[0]);
        split_pair(hA1.x, hA1.y, ah[1], am[1]);
        split_pair(hB0.x, hB0.y, ah[2], am[2]);
        split_pair(hB1.x, hB1.y, ah[3], am[3]);
        #pragma unroll
        for (int q=0;q<4;q++){
            const int nt = cgrp*4 + q;
            uint2 bh = g_W2Bh[nt*512 + ks*32 + lane];
            uint2 bm = g_W2Bm[nt*512 + ks*32 + lane];
            mma_bf16(acc2[q], ah, bh.x, bh.y);
            mma_bf16(acc2[q], ah, bm.x, bm.y);
            mma_bf16(acc2[q], am, bh.x, bh.y);
        }
    }
    __syncthreads();   // all old-S1 reads done before H2 overwrite

    #pragma unroll
    for (int q=0;q<4;q++){
        const int m0 = (cgrp*4 + q)*8 + 2*tg;
        float2 bb = *reinterpret_cast<const float2*>(&B2S[m0]);
        *reinterpret_cast<float2*>(&H2[ r0   *68 + m0]) =
            make_float2(fmaxf(acc2[q][0] + bb.x, 0.f), fmaxf(acc2[q][1] + bb.y, 0.f));
        *reinterpret_cast<float2*>(&H2[(r0+8)*68 + m0]) =
            make_float2(fmaxf(acc2[q][2] + bb.x, 0.f), fmaxf(acc2[q][3] + bb.y, 0.f));
    }
    __syncthreads();

    // ---- GEMM3 + penalties ----
    if (tid < 128){
        const int row = tid, i2 = row >> 6, j = row & 63;
        float s0=0.f, s1=0.f, s2=0.f, s3=0.f;
        #pragma unroll
        for (int c = 0; c < 64; c += 4){
            s0 = fmaf(H2[row*68 + c  ], W3S[c  ], s0);
            s1 = fmaf(H2[row*68 + c+1], W3S[c+1], s1);
            s2 = fmaf(H2[row*68 + c+2], W3S[c+2], s2);
            s3 = fmaf(H2[row*68 + c+3], W3S[c+3], s3);
        }
        float score = (s0+s1)+(s2+s3) + b3[0];
        if (alive_t [b*Nn + i0 + i2] < 0.5f) score -= PEN;
        if (alive_t1[b*Nn + j] < 0.5f) score -= PEN;
        float la = fminf(fmaxf(score, -PEN), PEN) * INV_TEMP;
        g_la[(b*Nn + i0 + i2)*Nn + j] = la;
    }
}

// ============ Kernel 3: Sinkhorn (1024 threads, 2 rows/warp) ============
__global__ void __launch_bounds__(1024) sinkhorn_kernel(
    const float* __restrict__ alive_t, const float* __restrict__ alive_t1,
    float* __restrict__ out)
{
    __shared__ float la[64][65];
    const int b = blockIdx.x;
    const int tid = threadIdx.x;
    const int lane = tid & 31, w = tid >> 5;   // 32 warps

    for (int idx = tid; idx < 64*64; idx += 1024)
        la[idx >> 6][idx & 63] = g_la[b*4096 + idx];
    __syncthreads();

    for (int it = 0; it < 20; it++){
        #pragma unroll
        for (int rr = 0; rr < 2; rr++){
            const int i = w*2 + rr;
            float v0 = la[i][lane], v1 = la[i][lane+32];
            float m = fmaxf(v0, v1);
            #pragma unroll
            for (int off = 16; off > 0; off >>= 1) m = fmaxf(m, __shfl_xor_sync(0xffffffffu, m, off));
            float s = __expf(v0 - m) + __expf(v1 - m);
            #pragma unroll
            for (int off = 16; off > 0; off >>= 1) s += __shfl_xor_sync(0xffffffffu, s, off);
            float lse = m + __logf(s);
            la[i][lane] = v0 - lse; la[i][lane+32] = v1 - lse;
        }
        __syncthreads();
        #pragma unroll
        for (int rr = 0; rr < 2; rr++){
            const int j = w*2 + rr;
            float v0 = la[lane][j], v1 = la[lane+32][j];
            float m = fmaxf(v0, v1);
            #pragma unroll
            for (int off = 16; off > 0; off >>= 1) m = fmaxf(m, __shfl_xor_sync(0xffffffffu, m, off));
            float s = __expf(v0 - m) + __expf(v1 - m);
            #pragma unroll
            for (int off = 16; off > 0; off >>= 1) s += __shfl_xor_sync(0xffffffffu, s, off);
            float lse = m + __logf(s);
            la[lane][j] = v0 - lse; la[lane+32][j] = v1 - lse;
        }
        __syncthreads();
    }
    #pragma unroll
    for (int rr = 0; rr < 2; rr++){
        const int i = w*2 + rr;
        float v0 = la[i][lane], v1 = la[i][lane+32];
        float bv; int bi;
        if (v1 > v0){ bv = v1; bi = lane + 32; } else { bv = v0; bi = lane; }
        #pragma unroll
        for (int off = 16; off > 0; off >>= 1){
            float ov = __shfl_xor_sync(0xffffffffu, bv, off);
            int   oi = __shfl_xor_sync(0xffffffffu, bi, off);
            if (ov > bv || (ov == bv && oi < bi)){ bv = ov; bi = oi; }
        }
        if (lane == 0){
            float conf = __expf(bv);
            float matched = (alive_t[b*Nn + i] > 0.5f && alive_t1[b*Nn + bi] > 0.5f && conf > 0.3f) ? 1.f : 0.f;
            out[b*Nn + i]         = (float)bi;
            out[Bb*Nn + b*Nn + i] = matched;
        }
    }
}

// ============ launch ============
extern "C" void kernel_launch(void* const* d_in, const int* in_sizes, int n_in,
                              void* d_out, int out_size)
{
    const float* slots_t  = (const float*)d_in[0];
    const float* slots_t1 = (const float*)d_in[1];
    const float* alive_t  = (const float*)d_in[2];
    const float* alive_t1 = (const float*)d_in[3];
    const float* W1 = (const float*)d_in[4];
    const float* b1 = (const float*)d_in[5];
    const float* W2 = (const float*)d_in[6];
    const float* b2 = (const float*)d_in[7];
    const float* W3 = (const float*)d_in[8];
    const float* b3 = (const float*)d_in[9];
    float* out = (float*)d_out;

    cudaFuncSetAttribute(precompute_kernel, cudaFuncAttributeMaxDynamicSharedMemorySize, P_SMEM_BYTES);
    cudaFuncSetAttribute(score_kernel,      cudaFuncAttributeMaxDynamicSharedMemorySize, Z_SMEM_BYTES);

    pack_weights<<<80, 256>>>(W1, W2);
    precompute_kernel<<<dim3(4, Bb), 512, P_SMEM_BYTES>>>(slots_t, slots_t1, W1, b1);
    score_kernel<<<dim3(Nn/2, Bb), 512, Z_SMEM_BYTES>>>(slots_t, slots_t1, alive_t, alive_t1,
                                                        b2, W3, b3);
    sinkhorn_kernel<<<Bb, 1024>>>(alive_t, alive_t1, out);
}